// round 14
// baseline (speedup 1.0000x reference)
#include <cuda_runtime.h>
#include <cuda_bf16.h>
#include <cuda_fp16.h>
#include <math.h>
#include <stdint.h>

#define B_   4
#define T_   1024
#define DIM_ 2048
#define NH   32
#define NKV  8
#define HD   64
#define NQKV (NH * HD + 2 * NKV * HD)   // 3072

// ---------------------------------------------------------------------------
// Scratch (__device__ globals; allocation-free rule)
// ---------------------------------------------------------------------------
__device__ __half g_xh[(size_t)B_ * T_ * DIM_];
__device__ __half g_wqkvh[(size_t)NQKV * DIM_];
__device__ __half g_woh[(size_t)DIM_ * NH * HD];

__device__ __half g_qh[(size_t)B_ * T_ * NH * HD];
__device__ __half g_ql[(size_t)B_ * T_ * NH * HD];
__device__ __half g_kh[(size_t)B_ * T_ * NKV * HD];
__device__ __half g_vh[(size_t)B_ * T_ * NKV * HD];
__device__ __half g_oh[(size_t)B_ * T_ * NH * HD];
__device__ __half g_ol[(size_t)B_ * T_ * NH * HD];

// Q scale folded with log2(e): 0.125 * 1.4426950408889634
#define QSCALE 0.18033688f

// ---------------------------------------------------------------------------
// PTX helpers
// ---------------------------------------------------------------------------
__device__ __forceinline__ uint32_t smem_u32(const void* p) {
    uint32_t a;
    asm("{ .reg .u64 t; cvta.to.shared.u64 t, %1; cvt.u32.u64 %0, t; }"
        : "=r"(a) : "l"(p));
    return a;
}

__device__ __forceinline__ void ldmx4(uint32_t* r, uint32_t addr) {
    asm volatile("ldmatrix.sync.aligned.m8n8.x4.shared.b16 {%0,%1,%2,%3}, [%4];"
                 : "=r"(r[0]), "=r"(r[1]), "=r"(r[2]), "=r"(r[3]) : "r"(addr));
}

__device__ __forceinline__ void ldmx4t(uint32_t* r, uint32_t addr) {
    asm volatile("ldmatrix.sync.aligned.m8n8.x4.trans.shared.b16 {%0,%1,%2,%3}, [%4];"
                 : "=r"(r[0]), "=r"(r[1]), "=r"(r[2]), "=r"(r[3]) : "r"(addr));
}

// fp16 MMA
__device__ __forceinline__ void mma_h(float* d, const uint32_t* a, const uint32_t* b) {
    asm volatile(
        "mma.sync.aligned.m16n8k16.row.col.f32.f16.f16.f32 "
        "{%0,%1,%2,%3}, {%4,%5,%6,%7}, {%8,%9}, {%0,%1,%2,%3};"
        : "+f"(d[0]), "+f"(d[1]), "+f"(d[2]), "+f"(d[3])
        : "r"(a[0]), "r"(a[1]), "r"(a[2]), "r"(a[3]), "r"(b[0]), "r"(b[1]));
}

__device__ __forceinline__ void cp16(uint32_t dst, const void* src) {
    asm volatile("cp.async.cg.shared.global [%0], [%1], 16;"
                 :: "r"(dst), "l"(src) : "memory");
}
#define CP_COMMIT() asm volatile("cp.async.commit_group;" ::: "memory")
#define CP_WAIT(n)  asm volatile("cp.async.wait_group %0;" :: "n"(n) : "memory")

__device__ __forceinline__ void split_store_h(__half* H, __half* L, size_t idx,
                                              float v0, float v1) {
    __half2 h = __floats2half2_rn(v0, v1);
    float2 f = __half22float2(h);
    __half2 l = __floats2half2_rn(v0 - f.x, v1 - f.y);
    *(__half2*)(H + idx) = h;
    *(__half2*)(L + idx) = l;
}

__device__ __forceinline__ void store_h2(__half* H, size_t idx, float v0, float v1) {
    *(__half2*)(H + idx) = __floats2half2_rn(v0, v1);
}

// ---------------------------------------------------------------------------
// Merged fp32 -> fp16 convert for all 5 tensors (one launch)
// ---------------------------------------------------------------------------
#define NX4  (B_ * T_ * DIM_ / 4)
#define NWQ4 (NH * HD * DIM_ / 4)
#define NWK4 (NKV * HD * DIM_ / 4)
#define NWO4 (DIM_ * NH * HD / 4)
#define NCVT (NX4 + NWQ4 + 2 * NWK4 + NWO4)

__global__ void cvt_all_kernel(const float4* __restrict__ x,
                               const float4* __restrict__ wq,
                               const float4* __restrict__ wk,
                               const float4* __restrict__ wv,
                               const float4* __restrict__ wo,
                               uint2* __restrict__ xh,
                               uint2* __restrict__ wqkvh,
                               uint2* __restrict__ woh)
{
    int i = blockIdx.x * blockDim.x + threadIdx.x;
    if (i >= NCVT) return;
    const float4* src;
    uint2* dst;
    if (i < NX4) {
        src = x + i; dst = xh + i;
    } else if (i < NX4 + NWQ4) {
        int j = i - NX4; src = wq + j; dst = wqkvh + j;
    } else if (i < NX4 + NWQ4 + NWK4) {
        int j = i - NX4 - NWQ4; src = wk + j; dst = wqkvh + NWQ4 + j;
    } else if (i < NX4 + NWQ4 + 2 * NWK4) {
        int j = i - NX4 - NWQ4 - NWK4; src = wv + j; dst = wqkvh + NWQ4 + NWK4 + j;
    } else {
        int j = i - NX4 - NWQ4 - 2 * NWK4; src = wo + j; dst = woh + j;
    }
    float4 a = *src;
    __half2 h0 = __floats2half2_rn(a.x, a.y);
    __half2 h1 = __floats2half2_rn(a.z, a.w);
    uint2 v;
    v.x = *(uint32_t*)&h0; v.y = *(uint32_t*)&h1;
    *dst = v;
}

// ---------------------------------------------------------------------------
// fp16 HMMA GEMM, 256x128 CTA tile, 8 warps 4(M)x2(N), warp tile 64x64.
// NP=1: C = A*B ; NP=2: C = Ah*B + Al*B. 2-stage cp.async.
// mode 0: fp32 C.  mode 1: fused QKV epilogue.
// ---------------------------------------------------------------------------
#define GBK 32
#define GST 40
#define ATB (256 * GST * 2)   // 20480 B  (A tile: 256 rows)
#define BTB (128 * GST * 2)   // 10240 B  (B tile: 128 rows)

template<int NP>
__global__ void __launch_bounds__(256, 1) gemm_h(
    const __half* __restrict__ Ah, const __half* __restrict__ Al,
    const __half* __restrict__ Bh,
    float* __restrict__ C, int M, int N, int K,
    const float* __restrict__ cosb, const float* __restrict__ sinb, int mode)
{
    constexpr uint32_t STAGE = NP * ATB + BTB;
    extern __shared__ __align__(16) __half smem[];
    const uint32_t uS = smem_u32(smem);

    const int tid  = threadIdx.x;
    const int wid  = tid >> 5;
    const int lane = tid & 31;
    const int m0 = blockIdx.y * 256;
    const int n0 = blockIdx.x * 128;

    const int wm = (wid & 3) * 64;    // 4 M-warps
    const int wn = (wid >> 2) * 64;   // 2 N-warps

    float acc[4][8][4];
#pragma unroll
    for (int i = 0; i < 4; i++)
#pragma unroll
        for (int j = 0; j < 8; j++)
#pragma unroll
            for (int c = 0; c < 4; c++) acc[i][j][c] = 0.0f;

    const int aRow = (lane & 7) + ((lane >> 3) & 1) * 8;
    const int aCol = (lane >> 4) * 8;
    const int bRow = (lane & 7) + (lane >> 4) * 8;
    const int bCol = ((lane >> 3) & 1) * 8;

    // gmem->smem: A row per thread (4 cp16); B row per thread-pair (2 cp16)
    const __half* gA_h = Ah + (size_t)(m0 + tid) * K;
    const __half* gA_l = (NP == 2) ? (Al + (size_t)(m0 + tid) * K) : nullptr;
    const __half* gB_h = Bh + (size_t)(n0 + (tid >> 1)) * K + (tid & 1) * 16;
    const uint32_t dA = uS + tid * (GST * 2);
    const uint32_t dB = uS + NP * ATB + (tid >> 1) * (GST * 2) + (tid & 1) * 32;

#define ISSUE_STAGE(buf, k0)                                               \
    {                                                                      \
        uint32_t a = dA + (buf) * STAGE;                                   \
        _Pragma("unroll")                                                  \
        for (int c = 0; c < 4; c++) {                                      \
            cp16(a + c * 16, gA_h + (k0) + c * 8);                         \
            if (NP == 2) cp16(a + ATB + c * 16, gA_l + (k0) + c * 8);      \
        }                                                                  \
        uint32_t bb = dB + (buf) * STAGE;                                  \
        cp16(bb,      gB_h + (k0));                                        \
        cp16(bb + 16, gB_h + (k0) + 8);                                    \
    }

    const int niter = K / GBK;
    ISSUE_STAGE(0, 0)
    CP_COMMIT();

    for (int it = 0; it < niter; it++) {
        const int buf = it & 1;
        CP_WAIT(0);
        __syncthreads();
        if (it + 1 < niter) {
            ISSUE_STAGE(buf ^ 1, (it + 1) * GBK)
            CP_COMMIT();
        }

        const uint32_t uAh = uS + buf * STAGE;
        const uint32_t uAl = uAh + ATB;
        const uint32_t uBh = uAh + NP * ATB;

#pragma unroll
        for (int kk = 0; kk < GBK; kk += 16) {
            uint32_t ah[4][4], al[4][4], bh[8][2];
#pragma unroll
            for (int mi = 0; mi < 4; mi++) {
                uint32_t off = (uint32_t)(((wm + mi * 16 + aRow) * GST + kk + aCol) * 2);
                ldmx4(ah[mi], uAh + off);
                if (NP == 2) ldmx4(al[mi], uAl + off);
            }
#pragma unroll
            for (int j = 0; j < 4; j++) {
                uint32_t off = (uint32_t)(((wn + j * 16 + bRow) * GST + kk + bCol) * 2);
                uint32_t rh[4];
                ldmx4(rh, uBh + off);
                bh[j * 2][0] = rh[0]; bh[j * 2][1] = rh[1];
                bh[j * 2 + 1][0] = rh[2]; bh[j * 2 + 1][1] = rh[3];
            }
#pragma unroll
            for (int mi = 0; mi < 4; mi++)
#pragma unroll
                for (int nj = 0; nj < 8; nj++) {
                    mma_h(acc[mi][nj], ah[mi], bh[nj]);
                    if (NP == 2) mma_h(acc[mi][nj], al[mi], bh[nj]);
                }
        }
    }
#undef ISSUE_STAGE

    const int er = lane >> 2;
    const int ec = (lane & 3) * 2;
#pragma unroll
    for (int mi = 0; mi < 4; mi++)
#pragma unroll
        for (int nj = 0; nj < 8; nj++) {
            float v0 = acc[mi][nj][0], v1 = acc[mi][nj][1];
            float v2 = acc[mi][nj][2], v3 = acc[mi][nj][3];
            const int gm = m0 + wm + mi * 16 + er;
            const int n  = n0 + wn + nj * 8 + ec;
            if (mode == 0) {
                float* p0 = C + (size_t)gm * N + n;
                *(float2*)p0           = make_float2(v0, v1);
                *(float2*)(p0 + 8 * N) = make_float2(v2, v3);
            } else {
                if (n < NH * HD + NKV * HD) {
                    const int p = (n & 63) >> 1;
                    const int t0 = gm & (T_ - 1);
                    const int t1 = (gm + 8) & (T_ - 1);
                    float c0 = cosb[t0 * 32 + p], s0 = sinb[t0 * 32 + p];
                    float c1 = cosb[t1 * 32 + p], s1 = sinb[t1 * 32 + p];
                    float e = v0, o = v1;
                    v0 = e * c0 - o * s0; v1 = e * s0 + o * c0;
                    e = v2; o = v3;
                    v2 = e * c1 - o * s1; v3 = e * s1 + o * c1;
                }
                if (n < NH * HD) {
                    v0 *= QSCALE; v1 *= QSCALE; v2 *= QSCALE; v3 *= QSCALE;
                    split_store_h(g_qh, g_ql, (size_t)gm * (NH * HD) + n, v0, v1);
                    split_store_h(g_qh, g_ql, (size_t)(gm + 8) * (NH * HD) + n, v2, v3);
                } else if (n < NH * HD + NKV * HD) {
                    int nn = n - NH * HD;
                    store_h2(g_kh, (size_t)gm * (NKV * HD) + nn, v0, v1);
                    store_h2(g_kh, (size_t)(gm + 8) * (NKV * HD) + nn, v2, v3);
                } else {
                    int nn = n - NH * HD - NKV * HD;
                    store_h2(g_vh, (size_t)gm * (NKV * HD) + nn, v0, v1);
                    store_h2(g_vh, (size_t)(gm + 8) * (NKV * HD) + nn, v2, v3);
                }
            }
        }
}

// ---------------------------------------------------------------------------
// Causal GQA flash attention, fp16 2-product, 2-stage KV pipeline (R13 core).
// ---------------------------------------------------------------------------
#define NEG_BIG (-1e30f)
#define AST 72
#define ATILE_B (64 * AST * 2)
#define ATTN_SMEM (4 * ATILE_B)   // 36864 B

__global__ void __launch_bounds__(128, 3) attn_hmma()
{
    const int qb = (T_ / 64 - 1) - blockIdx.x;   // long CTAs first
    const int bh = blockIdx.y;
    const int b = bh >> 5, h = bh & 31;
    const int kvh = h >> 2;

    extern __shared__ __align__(16) __half asm_[];
    const uint32_t uKV = smem_u32(asm_);

    const int tid  = threadIdx.x;
    const int wid  = tid >> 5;
    const int lane = tid & 31;

#define KVTILE(st, t) (uKV + (uint32_t)(((st) * 2 + (t)) * ATILE_B))

    const int aRow = (lane & 7) + ((lane >> 3) & 1) * 8;
    const int aCol = (lane >> 4) * 8;
    const int kRow = (lane & 7) + ((lane >> 4) & 1) * 8;
    const int kCol = ((lane >> 3) & 1) * 8;
    const int vRow = (lane & 7) + ((lane >> 3) & 1) * 8;
    const int vCol = ((lane >> 4) & 1) * 8;

    // --- prologue: stage Q (hi,lo) through stage-1 tiles, then release ---
    {
        const size_t qrow = ((size_t)(b * T_) + qb * 64);
        for (int f = tid; f < 512; f += 128) {
            int r = f >> 3, c = f & 7;
            size_t off = (qrow + r) * (NH * HD) + h * HD + c * 8;
            uint32_t d = (uint32_t)((r * AST + c * 8) * 2);
            cp16(KVTILE(1, 0) + d, g_qh + off);
            cp16(KVTILE(1, 1) + d, g_ql + off);
        }
    }
    CP_COMMIT();
    CP_WAIT(0);
    __syncthreads();

    uint32_t qh[4][4], ql[4][4];
#pragma unroll
    for (int kk = 0; kk < 4; kk++) {
        uint32_t off = (uint32_t)(((wid * 16 + aRow) * AST + kk * 16 + aCol) * 2);
        ldmx4(qh[kk], KVTILE(1, 0) + off);
        ldmx4(ql[kk], KVTILE(1, 1) + off);
    }
    __syncthreads();   // Q region free for KV reuse

#define ISSUE_KV(st, kb)                                                    \
    {                                                                       \
        size_t rowb = ((size_t)(b * T_) + (size_t)(kb) * 64);               \
        for (int f = tid; f < 512; f += 128) {                              \
            int r = f >> 3, c = f & 7;                                      \
            size_t off = (rowb + r) * (NKV * HD) + kvh * HD + c * 8;        \
            uint32_t d = (uint32_t)((r * AST + c * 8) * 2);                 \
            cp16(KVTILE(st, 0) + d, g_kh + off);                            \
            cp16(KVTILE(st, 1) + d, g_vh + off);                            \
        }                                                                   \
    }
    ISSUE_KV(0, 0)
    CP_COMMIT();

    float o[8][4];
#pragma unroll
    for (int j = 0; j < 8; j++)
#pragma unroll
        for (int c = 0; c < 4; c++) o[j][c] = 0.0f;
    float m[2] = {NEG_BIG, NEG_BIG}, l[2] = {0.0f, 0.0f};

    const int r0 = lane >> 2;
    const int c0 = (lane & 3) * 2;

    for (int kb = 0; kb <= qb; kb++) {
        CP_WAIT(0);
        __syncthreads();
        if (kb < qb) {
            ISSUE_KV((kb + 1) & 1, kb + 1)
            CP_COMMIT();
        }

        const uint32_t uKh = KVTILE(kb & 1, 0);
        const uint32_t uVh = KVTILE(kb & 1, 1);

        float s[8][4];
#pragma unroll
        for (int j = 0; j < 8; j++)
#pragma unroll
            for (int c = 0; c < 4; c++) s[j][c] = 0.0f;

#pragma unroll
        for (int kk = 0; kk < 4; kk++) {
#pragma unroll
            for (int g = 0; g < 4; g++) {
                uint32_t off = (uint32_t)(((g * 16 + kRow) * AST + kk * 16 + kCol) * 2);
                uint32_t kf[4];
                ldmx4(kf, uKh + off);
                mma_h(s[2 * g],     qh[kk], kf);
                mma_h(s[2 * g],     ql[kk], kf);
                mma_h(s[2 * g + 1], qh[kk], kf + 2);
                mma_h(s[2 * g + 1], ql[kk], kf + 2);
            }
        }

        if (kb == qb) {
            const int qr = wid * 16 + r0;
#pragma unroll
            for (int j = 0; j < 8; j++) {
                int col = j * 8 + c0;
                if (col     > qr)     s[j][0] = NEG_BIG;
                if (col + 1 > qr)     s[j][1] = NEG_BIG;
                if (col     > qr + 8) s[j][2] = NEG_BIG;
                if (col + 1 > qr + 8) s[j][3] = NEG_BIG;
            }
        }

        // online softmax in base-2
#pragma unroll
        for (int hh = 0; hh < 2; hh++) {
            float rm = NEG_BIG;
#pragma unroll
            for (int j = 0; j < 8; j++)
                rm = fmaxf(rm, fmaxf(s[j][2 * hh], s[j][2 * hh + 1]));
            rm = fmaxf(rm, __shfl_xor_sync(0xffffffffu, rm, 1));
            rm = fmaxf(rm, __shfl_xor_sync(0xffffffffu, rm, 2));
            float mnew = fmaxf(m[hh], rm);
            float corr = exp2f(m[hh] - mnew);
            float sum = 0.0f;
#pragma unroll
            for (int j = 0; j < 8; j++) {
                float p0 = exp2f(s[j][2 * hh]     - mnew);
                float p1 = exp2f(s[j][2 * hh + 1] - mnew);
                s[j][2 * hh] = p0; s[j][2 * hh + 1] = p1;
                sum += p0 + p1;
            }
            sum += __shfl_xor_sync(0xffffffffu, sum, 1);
            sum += __shfl_xor_sync(0xffffffffu, sum, 2);
            l[hh] = l[hh] * corr + sum;
            m[hh] = mnew;
#pragma unroll
            for (int j = 0; j < 8; j++) {
                o[j][2 * hh] *= corr; o[j][2 * hh + 1] *= corr;
            }
        }

        // PV: P split exact fp16 hi/lo, V single fp16
#pragma unroll
        for (int kk = 0; kk < 4; kk++) {
            uint32_t pha[4], pla[4];
#pragma unroll
            for (int t = 0; t < 2; t++) {
                int j = 2 * kk + t;
                __half2 hA = __floats2half2_rn(s[j][0], s[j][1]);
                float2 fA = __half22float2(hA);
                __half2 lA = __floats2half2_rn(s[j][0] - fA.x, s[j][1] - fA.y);
                __half2 hB = __floats2half2_rn(s[j][2], s[j][3]);
                float2 fB = __half22float2(hB);
                __half2 lB = __floats2half2_rn(s[j][2] - fB.x, s[j][3] - fB.y);
                pha[2 * t]     = *(uint32_t*)&hA;
                pha[2 * t + 1] = *(uint32_t*)&hB;
                pla[2 * t]     = *(uint32_t*)&lA;
                pla[2 * t + 1] = *(uint32_t*)&lB;
            }
#pragma unroll
            for (int g = 0; g < 4; g++) {
                uint32_t off = (uint32_t)(((kk * 16 + vRow) * AST + g * 16 + vCol) * 2);
                uint32_t vf[4];
                ldmx4t(vf, uVh + off);
                mma_h(o[2 * g],     pha, vf);
                mma_h(o[2 * g],     pla, vf);
                mma_h(o[2 * g + 1], pha, vf + 2);
                mma_h(o[2 * g + 1], pla, vf + 2);
            }
        }
    }
#undef ISSUE_KV
#undef KVTILE

#pragma unroll
    for (int hh = 0; hh < 2; hh++) {
        float inv = 1.0f / l[hh];
        size_t tok = (size_t)(b * T_) + qb * 64 + wid * 16 + r0 + hh * 8;
#pragma unroll
        for (int j = 0; j < 8; j++) {
            float v0 = o[j][2 * hh] * inv;
            float v1 = o[j][2 * hh + 1] * inv;
            size_t off = tok * (NH * HD) + h * HD + j * 8 + c0;
            split_store_h(g_oh, g_ol, off, v0, v1);
        }
    }
}

// ---------------------------------------------------------------------------
// Launch
// ---------------------------------------------------------------------------
extern "C" void kernel_launch(void* const* d_in, const int* in_sizes, int n_in,
                              void* d_out, int out_size)
{
    const float* x    = (const float*)d_in[0];
    const float* cosb = (const float*)d_in[1];
    const float* sinb = (const float*)d_in[2];
    const float* Wq   = (const float*)d_in[3];
    const float* Wk   = (const float*)d_in[4];
    const float* Wv   = (const float*)d_in[5];
    const float* Wo   = (const float*)d_in[6];
    float* out = (float*)d_out;

    __half *xh, *wqkvh, *woh, *oh, *ol;
    cudaGetSymbolAddress((void**)&xh, g_xh);
    cudaGetSymbolAddress((void**)&wqkvh, g_wqkvh);
    cudaGetSymbolAddress((void**)&woh, g_woh);
    cudaGetSymbolAddress((void**)&oh, g_oh);
    cudaGetSymbolAddress((void**)&ol, g_ol);

    cudaFuncSetAttribute(gemm_h<1>, cudaFuncAttributeMaxDynamicSharedMemorySize,
                         2 * (1 * ATB + BTB));     // 61440
    cudaFuncSetAttribute(gemm_h<2>, cudaFuncAttributeMaxDynamicSharedMemorySize,
                         2 * (2 * ATB + BTB));     // 102400
    cudaFuncSetAttribute(attn_hmma, cudaFuncAttributeMaxDynamicSharedMemorySize,
                         ATTN_SMEM);

    const int M = B_ * T_;  // 4096

    // Merged conversions
    cvt_all_kernel<<<(NCVT + 255) / 256, 256>>>(
        (const float4*)x, (const float4*)Wq, (const float4*)Wk,
        (const float4*)Wv, (const float4*)Wo,
        (uint2*)xh, (uint2*)wqkvh, (uint2*)woh);

    // Fused QKV projection (single fp16 product; RoPE/scale/split epilogue)
    gemm_h<1><<<dim3(NQKV / 128, M / 256), 256, 2 * (1 * ATB + BTB)>>>(
        xh, nullptr, wqkvh, nullptr, M, NQKV, DIM_, cosb, sinb, 1);

    // Attention (fp16 2-product HMMA, 2-stage KV pipeline)
    attn_hmma<<<dim3(T_ / 64, B_ * NH), 128, ATTN_SMEM>>>();

    // Output projection (fp16 2-product, exact A; 64x64 warp tiles) -> d_out
    gemm_h<2><<<dim3(DIM_ / 128, M / 256), 256, 2 * (2 * ATB + BTB)>>>(
        oh, ol, woh, out, M, DIM_, DIM_, cosb, sinb, 0);
}

// round 15
// speedup vs baseline: 1.1702x; 1.1702x over previous
#include <cuda_runtime.h>
#include <cuda_bf16.h>
#include <cuda_fp16.h>
#include <math.h>
#include <stdint.h>

#define B_   4
#define T_   1024
#define DIM_ 2048
#define NH   32
#define NKV  8
#define HD   64
#define NQKV (NH * HD + 2 * NKV * HD)   // 3072

// ---------------------------------------------------------------------------
// Scratch (__device__ globals; allocation-free rule)
// ---------------------------------------------------------------------------
__device__ __half g_xh[(size_t)B_ * T_ * DIM_];
__device__ __half g_wqkvh[(size_t)NQKV * DIM_];
__device__ __half g_woh[(size_t)DIM_ * NH * HD];

__device__ __half g_qh[(size_t)B_ * T_ * NH * HD];
__device__ __half g_ql[(size_t)B_ * T_ * NH * HD];
__device__ __half g_kh[(size_t)B_ * T_ * NKV * HD];
__device__ __half g_vh[(size_t)B_ * T_ * NKV * HD];
__device__ __half g_oh[(size_t)B_ * T_ * NH * HD];
__device__ __half g_ol[(size_t)B_ * T_ * NH * HD];

// Q scale folded with log2(e): 0.125 * 1.4426950408889634
#define QSCALE 0.18033688f

// ---------------------------------------------------------------------------
// PTX helpers
// ---------------------------------------------------------------------------
__device__ __forceinline__ uint32_t smem_u32(const void* p) {
    uint32_t a;
    asm("{ .reg .u64 t; cvta.to.shared.u64 t, %1; cvt.u32.u64 %0, t; }"
        : "=r"(a) : "l"(p));
    return a;
}

__device__ __forceinline__ void ldmx4(uint32_t* r, uint32_t addr) {
    asm volatile("ldmatrix.sync.aligned.m8n8.x4.shared.b16 {%0,%1,%2,%3}, [%4];"
                 : "=r"(r[0]), "=r"(r[1]), "=r"(r[2]), "=r"(r[3]) : "r"(addr));
}

__device__ __forceinline__ void ldmx4t(uint32_t* r, uint32_t addr) {
    asm volatile("ldmatrix.sync.aligned.m8n8.x4.trans.shared.b16 {%0,%1,%2,%3}, [%4];"
                 : "=r"(r[0]), "=r"(r[1]), "=r"(r[2]), "=r"(r[3]) : "r"(addr));
}

// fp16 MMA
__device__ __forceinline__ void mma_h(float* d, const uint32_t* a, const uint32_t* b) {
    asm volatile(
        "mma.sync.aligned.m16n8k16.row.col.f32.f16.f16.f32 "
        "{%0,%1,%2,%3}, {%4,%5,%6,%7}, {%8,%9}, {%0,%1,%2,%3};"
        : "+f"(d[0]), "+f"(d[1]), "+f"(d[2]), "+f"(d[3])
        : "r"(a[0]), "r"(a[1]), "r"(a[2]), "r"(a[3]), "r"(b[0]), "r"(b[1]));
}

__device__ __forceinline__ void cp16(uint32_t dst, const void* src) {
    asm volatile("cp.async.cg.shared.global [%0], [%1], 16;"
                 :: "r"(dst), "l"(src) : "memory");
}
#define CP_COMMIT() asm volatile("cp.async.commit_group;" ::: "memory")
#define CP_WAIT(n)  asm volatile("cp.async.wait_group %0;" :: "n"(n) : "memory")

__device__ __forceinline__ void split_store_h(__half* H, __half* L, size_t idx,
                                              float v0, float v1) {
    __half2 h = __floats2half2_rn(v0, v1);
    float2 f = __half22float2(h);
    __half2 l = __floats2half2_rn(v0 - f.x, v1 - f.y);
    *(__half2*)(H + idx) = h;
    *(__half2*)(L + idx) = l;
}

__device__ __forceinline__ void store_h2(__half* H, size_t idx, float v0, float v1) {
    *(__half2*)(H + idx) = __floats2half2_rn(v0, v1);
}

// ---------------------------------------------------------------------------
// Merged fp32 -> fp16 convert for all 5 tensors (one launch)
// ---------------------------------------------------------------------------
#define NX4  (B_ * T_ * DIM_ / 4)
#define NWQ4 (NH * HD * DIM_ / 4)
#define NWK4 (NKV * HD * DIM_ / 4)
#define NWO4 (DIM_ * NH * HD / 4)
#define NCVT (NX4 + NWQ4 + 2 * NWK4 + NWO4)

__global__ void cvt_all_kernel(const float4* __restrict__ x,
                               const float4* __restrict__ wq,
                               const float4* __restrict__ wk,
                               const float4* __restrict__ wv,
                               const float4* __restrict__ wo,
                               uint2* __restrict__ xh,
                               uint2* __restrict__ wqkvh,
                               uint2* __restrict__ woh)
{
    int i = blockIdx.x * blockDim.x + threadIdx.x;
    if (i >= NCVT) return;
    const float4* src;
    uint2* dst;
    if (i < NX4) {
        src = x + i; dst = xh + i;
    } else if (i < NX4 + NWQ4) {
        int j = i - NX4; src = wq + j; dst = wqkvh + j;
    } else if (i < NX4 + NWQ4 + NWK4) {
        int j = i - NX4 - NWQ4; src = wk + j; dst = wqkvh + NWQ4 + j;
    } else if (i < NX4 + NWQ4 + 2 * NWK4) {
        int j = i - NX4 - NWQ4 - NWK4; src = wv + j; dst = wqkvh + NWQ4 + NWK4 + j;
    } else {
        int j = i - NX4 - NWQ4 - 2 * NWK4; src = wo + j; dst = woh + j;
    }
    float4 a = *src;
    __half2 h0 = __floats2half2_rn(a.x, a.y);
    __half2 h1 = __floats2half2_rn(a.z, a.w);
    uint2 v;
    v.x = *(uint32_t*)&h0; v.y = *(uint32_t*)&h1;
    *dst = v;
}

// ---------------------------------------------------------------------------
// fp16 HMMA GEMM (R13 config), 2-stage cp.async pipeline.
// Warp layout:
//   NP==1: 2(M) x 4(N) warps, warp tile 64x32
//   NP==2: 4(M) x 2(N) warps, warp tile 32x64 (128 B/MMA)
// mode 0: fp32 C.  mode 1: fused QKV epilogue.
// ---------------------------------------------------------------------------
#define GBK 32
#define GST 40
#define TILE_B  (128 * GST * 2)          // 10240 B

template<int NP>
__global__ __launch_bounds__(256) void gemm_h(
    const __half* __restrict__ Ah, const __half* __restrict__ Al,
    const __half* __restrict__ Bh,
    float* __restrict__ C, int M, int N, int K,
    const float* __restrict__ cosb, const float* __restrict__ sinb, int mode)
{
    constexpr uint32_t STAGE = (NP + 1) * TILE_B;
    constexpr int MT = (NP == 2) ? 2 : 4;
    constexpr int NT = (NP == 2) ? 8 : 4;

    extern __shared__ __align__(16) __half smem[];
    const uint32_t uS = smem_u32(smem);

    const int tid  = threadIdx.x;
    const int wid  = tid >> 5;
    const int lane = tid & 31;
    const int m0 = blockIdx.y * 128;
    const int n0 = blockIdx.x * 128;

    const int wm = (NP == 2) ? (wid & 3) * 32 : (wid & 1) * 64;
    const int wn = (NP == 2) ? (wid >> 2) * 64 : (wid >> 1) * 32;

    float acc[MT][NT][4];
#pragma unroll
    for (int i = 0; i < MT; i++)
#pragma unroll
        for (int j = 0; j < NT; j++)
#pragma unroll
            for (int c = 0; c < 4; c++) acc[i][j][c] = 0.0f;

    const int aRow = (lane & 7) + ((lane >> 3) & 1) * 8;
    const int aCol = (lane >> 4) * 8;
    const int bRow = (lane & 7) + (lane >> 4) * 8;
    const int bCol = ((lane >> 3) & 1) * 8;

    const int lr = tid >> 1;
    const int lc = (tid & 1) * 2;

    const __half* gA_h = Ah + (size_t)(m0 + lr) * K + lc * 8;
    const __half* gA_l = (NP == 2) ? (Al + (size_t)(m0 + lr) * K + lc * 8) : nullptr;
    const __half* gB_h = Bh + (size_t)(n0 + lr) * K + lc * 8;
    const uint32_t dRow = uS + lr * (GST * 2) + lc * 16;

#define ISSUE_STAGE(buf, k0)                                               \
    {                                                                      \
        uint32_t d = dRow + (buf) * STAGE;                                 \
        cp16(d,       gA_h + (k0));                                        \
        cp16(d + 16,  gA_h + (k0) + 8);                                    \
        if (NP == 2) {                                                     \
            cp16(d + TILE_B,      gA_l + (k0));                            \
            cp16(d + TILE_B + 16, gA_l + (k0) + 8);                        \
        }                                                                  \
        cp16(d + NP * TILE_B,      gB_h + (k0));                           \
        cp16(d + NP * TILE_B + 16, gB_h + (k0) + 8);                       \
    }

    const int niter = K / GBK;
    ISSUE_STAGE(0, 0)
    CP_COMMIT();

    for (int it = 0; it < niter; it++) {
        const int buf = it & 1;
        CP_WAIT(0);
        __syncthreads();
        if (it + 1 < niter) {
            ISSUE_STAGE(buf ^ 1, (it + 1) * GBK)
            CP_COMMIT();
        }

        const uint32_t uAh = uS + buf * STAGE;
        const uint32_t uAl = uAh + TILE_B;
        const uint32_t uBh = uAh + NP * TILE_B;

#pragma unroll
        for (int kk = 0; kk < GBK; kk += 16) {
            uint32_t ah[MT][4], al[MT][4], bh[NT][2];
#pragma unroll
            for (int mi = 0; mi < MT; mi++) {
                uint32_t off = (uint32_t)(((wm + mi * 16 + aRow) * GST + kk + aCol) * 2);
                ldmx4(ah[mi], uAh + off);
                if (NP == 2) ldmx4(al[mi], uAl + off);
            }
#pragma unroll
            for (int j = 0; j < NT / 2; j++) {
                uint32_t off = (uint32_t)(((wn + j * 16 + bRow) * GST + kk + bCol) * 2);
                uint32_t rh[4];
                ldmx4(rh, uBh + off);
                bh[j * 2][0] = rh[0]; bh[j * 2][1] = rh[1];
                bh[j * 2 + 1][0] = rh[2]; bh[j * 2 + 1][1] = rh[3];
            }
#pragma unroll
            for (int mi = 0; mi < MT; mi++)
#pragma unroll
                for (int nj = 0; nj < NT; nj++) {
                    mma_h(acc[mi][nj], ah[mi], bh[nj]);
                    if (NP == 2) mma_h(acc[mi][nj], al[mi], bh[nj]);
                }
        }
    }
#undef ISSUE_STAGE

    const int er = lane >> 2;
    const int ec = (lane & 3) * 2;
#pragma unroll
    for (int mi = 0; mi < MT; mi++)
#pragma unroll
        for (int nj = 0; nj < NT; nj++) {
            float v0 = acc[mi][nj][0], v1 = acc[mi][nj][1];
            float v2 = acc[mi][nj][2], v3 = acc[mi][nj][3];
            const int gm = m0 + wm + mi * 16 + er;
            const int n  = n0 + wn + nj * 8 + ec;
            if (mode == 0) {
                float* p0 = C + (size_t)gm * N + n;
                *(float2*)p0           = make_float2(v0, v1);
                *(float2*)(p0 + 8 * N) = make_float2(v2, v3);
            } else {
                if (n < NH * HD + NKV * HD) {
                    const int p = (n & 63) >> 1;
                    const int t0 = gm & (T_ - 1);
                    const int t1 = (gm + 8) & (T_ - 1);
                    float c0 = cosb[t0 * 32 + p], s0 = sinb[t0 * 32 + p];
                    float c1 = cosb[t1 * 32 + p], s1 = sinb[t1 * 32 + p];
                    float e = v0, o = v1;
                    v0 = e * c0 - o * s0; v1 = e * s0 + o * c0;
                    e = v2; o = v3;
                    v2 = e * c1 - o * s1; v3 = e * s1 + o * c1;
                }
                if (n < NH * HD) {
                    v0 *= QSCALE; v1 *= QSCALE; v2 *= QSCALE; v3 *= QSCALE;
                    split_store_h(g_qh, g_ql, (size_t)gm * (NH * HD) + n, v0, v1);
                    split_store_h(g_qh, g_ql, (size_t)(gm + 8) * (NH * HD) + n, v2, v3);
                } else if (n < NH * HD + NKV * HD) {
                    int nn = n - NH * HD;
                    store_h2(g_kh, (size_t)gm * (NKV * HD) + nn, v0, v1);
                    store_h2(g_kh, (size_t)(gm + 8) * (NKV * HD) + nn, v2, v3);
                } else {
                    int nn = n - NH * HD - NKV * HD;
                    store_h2(g_vh, (size_t)gm * (NKV * HD) + nn, v0, v1);
                    store_h2(g_vh, (size_t)(gm + 8) * (NKV * HD) + nn, v2, v3);
                }
            }
        }
}

// ---------------------------------------------------------------------------
// Causal GQA flash attention, fp16 2-product, 2-stage KV pipeline.
// Now 4 CTAs/SM (smem 36.9KB, regs capped by launch bounds).
// ---------------------------------------------------------------------------
#define NEG_BIG (-1e30f)
#define AST 72
#define ATILE_B (64 * AST * 2)
#define ATTN_SMEM (4 * ATILE_B)   // 36864 B

__global__ void __launch_bounds__(128, 4) attn_hmma()
{
    const int qb = (T_ / 64 - 1) - blockIdx.x;   // long CTAs first
    const int bh = blockIdx.y;
    const int b = bh >> 5, h = bh & 31;
    const int kvh = h >> 2;

    extern __shared__ __align__(16) __half asm_[];
    const uint32_t uKV = smem_u32(asm_);

    const int tid  = threadIdx.x;
    const int wid  = tid >> 5;
    const int lane = tid & 31;

#define KVTILE(st, t) (uKV + (uint32_t)(((st) * 2 + (t)) * ATILE_B))

    const int aRow = (lane & 7) + ((lane >> 3) & 1) * 8;
    const int aCol = (lane >> 4) * 8;
    const int kRow = (lane & 7) + ((lane >> 4) & 1) * 8;
    const int kCol = ((lane >> 3) & 1) * 8;
    const int vRow = (lane & 7) + ((lane >> 3) & 1) * 8;
    const int vCol = ((lane >> 4) & 1) * 8;

    // --- prologue: stage Q (hi,lo) through stage-1 tiles, then release ---
    {
        const size_t qrow = ((size_t)(b * T_) + qb * 64);
        for (int f = tid; f < 512; f += 128) {
            int r = f >> 3, c = f & 7;
            size_t off = (qrow + r) * (NH * HD) + h * HD + c * 8;
            uint32_t d = (uint32_t)((r * AST + c * 8) * 2);
            cp16(KVTILE(1, 0) + d, g_qh + off);
            cp16(KVTILE(1, 1) + d, g_ql + off);
        }
    }
    CP_COMMIT();
    CP_WAIT(0);
    __syncthreads();

    uint32_t qh[4][4], ql[4][4];
#pragma unroll
    for (int kk = 0; kk < 4; kk++) {
        uint32_t off = (uint32_t)(((wid * 16 + aRow) * AST + kk * 16 + aCol) * 2);
        ldmx4(qh[kk], KVTILE(1, 0) + off);
        ldmx4(ql[kk], KVTILE(1, 1) + off);
    }
    __syncthreads();   // Q region free for KV reuse

#define ISSUE_KV(st, kb)                                                    \
    {                                                                       \
        size_t rowb = ((size_t)(b * T_) + (size_t)(kb) * 64);               \
        for (int f = tid; f < 512; f += 128) {                              \
            int r = f >> 3, c = f & 7;                                      \
            size_t off = (rowb + r) * (NKV * HD) + kvh * HD + c * 8;        \
            uint32_t d = (uint32_t)((r * AST + c * 8) * 2);                 \
            cp16(KVTILE(st, 0) + d, g_kh + off);                            \
            cp16(KVTILE(st, 1) + d, g_vh + off);                            \
        }                                                                   \
    }
    ISSUE_KV(0, 0)
    CP_COMMIT();

    float o[8][4];
#pragma unroll
    for (int j = 0; j < 8; j++)
#pragma unroll
        for (int c = 0; c < 4; c++) o[j][c] = 0.0f;
    float m[2] = {NEG_BIG, NEG_BIG}, l[2] = {0.0f, 0.0f};

    const int r0 = lane >> 2;
    const int c0 = (lane & 3) * 2;

    for (int kb = 0; kb <= qb; kb++) {
        CP_WAIT(0);
        __syncthreads();
        if (kb < qb) {
            ISSUE_KV((kb + 1) & 1, kb + 1)
            CP_COMMIT();
        }

        const uint32_t uKh = KVTILE(kb & 1, 0);
        const uint32_t uVh = KVTILE(kb & 1, 1);

        float s[8][4];
#pragma unroll
        for (int j = 0; j < 8; j++)
#pragma unroll
            for (int c = 0; c < 4; c++) s[j][c] = 0.0f;

#pragma unroll
        for (int kk = 0; kk < 4; kk++) {
#pragma unroll
            for (int g = 0; g < 4; g++) {
                uint32_t off = (uint32_t)(((g * 16 + kRow) * AST + kk * 16 + kCol) * 2);
                uint32_t kf[4];
                ldmx4(kf, uKh + off);
                mma_h(s[2 * g],     qh[kk], kf);
                mma_h(s[2 * g],     ql[kk], kf);
                mma_h(s[2 * g + 1], qh[kk], kf + 2);
                mma_h(s[2 * g + 1], ql[kk], kf + 2);
            }
        }

        if (kb == qb) {
            const int qr = wid * 16 + r0;
#pragma unroll
            for (int j = 0; j < 8; j++) {
                int col = j * 8 + c0;
                if (col     > qr)     s[j][0] = NEG_BIG;
                if (col + 1 > qr)     s[j][1] = NEG_BIG;
                if (col     > qr + 8) s[j][2] = NEG_BIG;
                if (col + 1 > qr + 8) s[j][3] = NEG_BIG;
            }
        }

        // online softmax in base-2
#pragma unroll
        for (int hh = 0; hh < 2; hh++) {
            float rm = NEG_BIG;
#pragma unroll
            for (int j = 0; j < 8; j++)
                rm = fmaxf(rm, fmaxf(s[j][2 * hh], s[j][2 * hh + 1]));
            rm = fmaxf(rm, __shfl_xor_sync(0xffffffffu, rm, 1));
            rm = fmaxf(rm, __shfl_xor_sync(0xffffffffu, rm, 2));
            float mnew = fmaxf(m[hh], rm);
            float corr = exp2f(m[hh] - mnew);
            float sum = 0.0f;
#pragma unroll
            for (int j = 0; j < 8; j++) {
                float p0 = exp2f(s[j][2 * hh]     - mnew);
                float p1 = exp2f(s[j][2 * hh + 1] - mnew);
                s[j][2 * hh] = p0; s[j][2 * hh + 1] = p1;
                sum += p0 + p1;
            }
            sum += __shfl_xor_sync(0xffffffffu, sum, 1);
            sum += __shfl_xor_sync(0xffffffffu, sum, 2);
            l[hh] = l[hh] * corr + sum;
            m[hh] = mnew;
#pragma unroll
            for (int j = 0; j < 8; j++) {
                o[j][2 * hh] *= corr; o[j][2 * hh + 1] *= corr;
            }
        }

        // PV: P split exact fp16 hi/lo, V single fp16
#pragma unroll
        for (int kk = 0; kk < 4; kk++) {
            uint32_t pha[4], pla[4];
#pragma unroll
            for (int t = 0; t < 2; t++) {
                int j = 2 * kk + t;
                __half2 hA = __floats2half2_rn(s[j][0], s[j][1]);
                float2 fA = __half22float2(hA);
                __half2 lA = __floats2half2_rn(s[j][0] - fA.x, s[j][1] - fA.y);
                __half2 hB = __floats2half2_rn(s[j][2], s[j][3]);
                float2 fB = __half22float2(hB);
                __half2 lB = __floats2half2_rn(s[j][2] - fB.x, s[j][3] - fB.y);
                pha[2 * t]     = *(uint32_t*)&hA;
                pha[2 * t + 1] = *(uint32_t*)&hB;
                pla[2 * t]     = *(uint32_t*)&lA;
                pla[2 * t + 1] = *(uint32_t*)&lB;
            }
#pragma unroll
            for (int g = 0; g < 4; g++) {
                uint32_t off = (uint32_t)(((kk * 16 + vRow) * AST + g * 16 + vCol) * 2);
                uint32_t vf[4];
                ldmx4t(vf, uVh + off);
                mma_h(o[2 * g],     pha, vf);
                mma_h(o[2 * g],     pla, vf);
                mma_h(o[2 * g + 1], pha, vf + 2);
                mma_h(o[2 * g + 1], pla, vf + 2);
            }
        }
    }
#undef ISSUE_KV
#undef KVTILE

#pragma unroll
    for (int hh = 0; hh < 2; hh++) {
        float inv = 1.0f / l[hh];
        size_t tok = (size_t)(b * T_) + qb * 64 + wid * 16 + r0 + hh * 8;
#pragma unroll
        for (int j = 0; j < 8; j++) {
            float v0 = o[j][2 * hh] * inv;
            float v1 = o[j][2 * hh + 1] * inv;
            size_t off = tok * (NH * HD) + h * HD + j * 8 + c0;
            split_store_h(g_oh, g_ol, off, v0, v1);
        }
    }
}

// ---------------------------------------------------------------------------
// Launch
// ---------------------------------------------------------------------------
extern "C" void kernel_launch(void* const* d_in, const int* in_sizes, int n_in,
                              void* d_out, int out_size)
{
    const float* x    = (const float*)d_in[0];
    const float* cosb = (const float*)d_in[1];
    const float* sinb = (const float*)d_in[2];
    const float* Wq   = (const float*)d_in[3];
    const float* Wk   = (const float*)d_in[4];
    const float* Wv   = (const float*)d_in[5];
    const float* Wo   = (const float*)d_in[6];
    float* out = (float*)d_out;

    __half *xh, *wqkvh, *woh, *oh, *ol;
    cudaGetSymbolAddress((void**)&xh, g_xh);
    cudaGetSymbolAddress((void**)&wqkvh, g_wqkvh);
    cudaGetSymbolAddress((void**)&woh, g_woh);
    cudaGetSymbolAddress((void**)&oh, g_oh);
    cudaGetSymbolAddress((void**)&ol, g_ol);

    cudaFuncSetAttribute(gemm_h<1>, cudaFuncAttributeMaxDynamicSharedMemorySize,
                         2 * 2 * TILE_B);
    cudaFuncSetAttribute(gemm_h<2>, cudaFuncAttributeMaxDynamicSharedMemorySize,
                         2 * 3 * TILE_B);
    cudaFuncSetAttribute(attn_hmma, cudaFuncAttributeMaxDynamicSharedMemorySize,
                         ATTN_SMEM);

    const int M = B_ * T_;  // 4096

    // Merged conversions
    cvt_all_kernel<<<(NCVT + 255) / 256, 256>>>(
        (const float4*)x, (const float4*)Wq, (const float4*)Wk,
        (const float4*)Wv, (const float4*)Wo,
        (uint2*)xh, (uint2*)wqkvh, (uint2*)woh);

    // Fused QKV projection (single fp16 product; RoPE/scale/split epilogue)
    gemm_h<1><<<dim3(NQKV / 128, M / 128), 256, 2 * 2 * TILE_B>>>(
        xh, nullptr, wqkvh, nullptr, M, NQKV, DIM_, cosb, sinb, 1);

    // Attention (fp16 2-product HMMA, 2-stage KV pipeline, 4 CTAs/SM)
    attn_hmma<<<dim3(T_ / 64, B_ * NH), 128, ATTN_SMEM>>>();

    // Output projection (fp16 2-product, exact A; 4Mx2N warp layout) -> d_out
    gemm_h<2><<<dim3(DIM_ / 128, M / 128), 256, 2 * 3 * TILE_B>>>(
        oh, ol, woh, out, M, DIM_, DIM_, cosb, sinb, 0);
}

// round 16
// speedup vs baseline: 1.4829x; 1.2672x over previous
#include <cuda_runtime.h>
#include <cuda_bf16.h>
#include <cuda_fp16.h>
#include <math.h>
#include <stdint.h>

#define B_   4
#define T_   1024
#define DIM_ 2048
#define NH   32
#define NKV  8
#define HD   64
#define NQKV (NH * HD + 2 * NKV * HD)   // 3072

// ---------------------------------------------------------------------------
// Scratch (__device__ globals; allocation-free rule)
// ---------------------------------------------------------------------------
__device__ __half g_xh[(size_t)B_ * T_ * DIM_];
__device__ __half g_wqkvh[(size_t)NQKV * DIM_];
__device__ __half g_woh[(size_t)DIM_ * NH * HD];

__device__ __half g_qh[(size_t)B_ * T_ * NH * HD];
__device__ __half g_ql[(size_t)B_ * T_ * NH * HD];
__device__ __half g_kh[(size_t)B_ * T_ * NKV * HD];
__device__ __half g_vh[(size_t)B_ * T_ * NKV * HD];
__device__ __half g_oh[(size_t)B_ * T_ * NH * HD];

// Q scale folded with log2(e): 0.125 * 1.4426950408889634
#define QSCALE 0.18033688f

// ---------------------------------------------------------------------------
// PTX helpers
// ---------------------------------------------------------------------------
__device__ __forceinline__ uint32_t smem_u32(const void* p) {
    uint32_t a;
    asm("{ .reg .u64 t; cvta.to.shared.u64 t, %1; cvt.u32.u64 %0, t; }"
        : "=r"(a) : "l"(p));
    return a;
}

__device__ __forceinline__ void ldmx4(uint32_t* r, uint32_t addr) {
    asm volatile("ldmatrix.sync.aligned.m8n8.x4.shared.b16 {%0,%1,%2,%3}, [%4];"
                 : "=r"(r[0]), "=r"(r[1]), "=r"(r[2]), "=r"(r[3]) : "r"(addr));
}

__device__ __forceinline__ void ldmx4t(uint32_t* r, uint32_t addr) {
    asm volatile("ldmatrix.sync.aligned.m8n8.x4.trans.shared.b16 {%0,%1,%2,%3}, [%4];"
                 : "=r"(r[0]), "=r"(r[1]), "=r"(r[2]), "=r"(r[3]) : "r"(addr));
}

// fp16 MMA
__device__ __forceinline__ void mma_h(float* d, const uint32_t* a, const uint32_t* b) {
    asm volatile(
        "mma.sync.aligned.m16n8k16.row.col.f32.f16.f16.f32 "
        "{%0,%1,%2,%3}, {%4,%5,%6,%7}, {%8,%9}, {%0,%1,%2,%3};"
        : "+f"(d[0]), "+f"(d[1]), "+f"(d[2]), "+f"(d[3])
        : "r"(a[0]), "r"(a[1]), "r"(a[2]), "r"(a[3]), "r"(b[0]), "r"(b[1]));
}

__device__ __forceinline__ void cp16(uint32_t dst, const void* src) {
    asm volatile("cp.async.cg.shared.global [%0], [%1], 16;"
                 :: "r"(dst), "l"(src) : "memory");
}
#define CP_COMMIT() asm volatile("cp.async.commit_group;" ::: "memory")
#define CP_WAIT(n)  asm volatile("cp.async.wait_group %0;" :: "n"(n) : "memory")

__device__ __forceinline__ void split_store_h(__half* H, __half* L, size_t idx,
                                              float v0, float v1) {
    __half2 h = __floats2half2_rn(v0, v1);
    float2 f = __half22float2(h);
    __half2 l = __floats2half2_rn(v0 - f.x, v1 - f.y);
    *(__half2*)(H + idx) = h;
    *(__half2*)(L + idx) = l;
}

__device__ __forceinline__ void store_h2(__half* H, size_t idx, float v0, float v1) {
    *(__half2*)(H + idx) = __floats2half2_rn(v0, v1);
}

// ---------------------------------------------------------------------------
// Merged fp32 -> fp16 convert for all 5 tensors (one launch)
// ---------------------------------------------------------------------------
#define NX4  (B_ * T_ * DIM_ / 4)
#define NWQ4 (NH * HD * DIM_ / 4)
#define NWK4 (NKV * HD * DIM_ / 4)
#define NWO4 (DIM_ * NH * HD / 4)
#define NCVT (NX4 + NWQ4 + 2 * NWK4 + NWO4)

__global__ void cvt_all_kernel(const float4* __restrict__ x,
                               const float4* __restrict__ wq,
                               const float4* __restrict__ wk,
                               const float4* __restrict__ wv,
                               const float4* __restrict__ wo,
                               uint2* __restrict__ xh,
                               uint2* __restrict__ wqkvh,
                               uint2* __restrict__ woh)
{
    int i = blockIdx.x * blockDim.x + threadIdx.x;
    if (i >= NCVT) return;
    const float4* src;
    uint2* dst;
    if (i < NX4) {
        src = x + i; dst = xh + i;
    } else if (i < NX4 + NWQ4) {
        int j = i - NX4; src = wq + j; dst = wqkvh + j;
    } else if (i < NX4 + NWQ4 + NWK4) {
        int j = i - NX4 - NWQ4; src = wk + j; dst = wqkvh + NWQ4 + j;
    } else if (i < NX4 + NWQ4 + 2 * NWK4) {
        int j = i - NX4 - NWQ4 - NWK4; src = wv + j; dst = wqkvh + NWQ4 + NWK4 + j;
    } else {
        int j = i - NX4 - NWQ4 - 2 * NWK4; src = wo + j; dst = woh + j;
    }
    float4 a = *src;
    __half2 h0 = __floats2half2_rn(a.x, a.y);
    __half2 h1 = __floats2half2_rn(a.z, a.w);
    uint2 v;
    v.x = *(uint32_t*)&h0; v.y = *(uint32_t*)&h1;
    *dst = v;
}

// ---------------------------------------------------------------------------
// fp16 HMMA GEMM (R13 config), 2-stage cp.async pipeline.
// Warp layout:
//   NP==1: 2(M) x 4(N) warps, warp tile 64x32 (192 B/MMA)
//   NP==2: 4(M) x 2(N) warps, warp tile 32x64 (128 B/MMA)
// mode 0: fp32 C.  mode 1: fused QKV epilogue.
// ---------------------------------------------------------------------------
#define GBK 32
#define GST 40
#define TILE_B  (128 * GST * 2)          // 10240 B

template<int NP>
__global__ __launch_bounds__(256, 2) void gemm_h(
    const __half* __restrict__ Ah, const __half* __restrict__ Al,
    const __half* __restrict__ Bh,
    float* __restrict__ C, int M, int N, int K,
    const float* __restrict__ cosb, const float* __restrict__ sinb, int mode)
{
    constexpr uint32_t STAGE = (NP + 1) * TILE_B;
    constexpr int MT = (NP == 2) ? 2 : 4;
    constexpr int NT = (NP == 2) ? 8 : 4;

    extern __shared__ __align__(16) __half smem[];
    const uint32_t uS = smem_u32(smem);

    const int tid  = threadIdx.x;
    const int wid  = tid >> 5;
    const int lane = tid & 31;
    const int m0 = blockIdx.y * 128;
    const int n0 = blockIdx.x * 128;

    const int wm = (NP == 2) ? (wid & 3) * 32 : (wid & 1) * 64;
    const int wn = (NP == 2) ? (wid >> 2) * 64 : (wid >> 1) * 32;

    float acc[MT][NT][4];
#pragma unroll
    for (int i = 0; i < MT; i++)
#pragma unroll
        for (int j = 0; j < NT; j++)
#pragma unroll
            for (int c = 0; c < 4; c++) acc[i][j][c] = 0.0f;

    const int aRow = (lane & 7) + ((lane >> 3) & 1) * 8;
    const int aCol = (lane >> 4) * 8;
    const int bRow = (lane & 7) + (lane >> 4) * 8;
    const int bCol = ((lane >> 3) & 1) * 8;

    const int lr = tid >> 1;
    const int lc = (tid & 1) * 2;

    const __half* gA_h = Ah + (size_t)(m0 + lr) * K + lc * 8;
    const __half* gA_l = (NP == 2) ? (Al + (size_t)(m0 + lr) * K + lc * 8) : nullptr;
    const __half* gB_h = Bh + (size_t)(n0 + lr) * K + lc * 8;
    const uint32_t dRow = uS + lr * (GST * 2) + lc * 16;

#define ISSUE_STAGE(buf, k0)                                               \
    {                                                                      \
        uint32_t d = dRow + (buf) * STAGE;                                 \
        cp16(d,       gA_h + (k0));                                        \
        cp16(d + 16,  gA_h + (k0) + 8);                                    \
        if (NP == 2) {                                                     \
            cp16(d + TILE_B,      gA_l + (k0));                            \
            cp16(d + TILE_B + 16, gA_l + (k0) + 8);                        \
        }                                                                  \
        cp16(d + NP * TILE_B,      gB_h + (k0));                           \
        cp16(d + NP * TILE_B + 16, gB_h + (k0) + 8);                       \
    }

    const int niter = K / GBK;
    ISSUE_STAGE(0, 0)
    CP_COMMIT();

    for (int it = 0; it < niter; it++) {
        const int buf = it & 1;
        CP_WAIT(0);
        __syncthreads();
        if (it + 1 < niter) {
            ISSUE_STAGE(buf ^ 1, (it + 1) * GBK)
            CP_COMMIT();
        }

        const uint32_t uAh = uS + buf * STAGE;
        const uint32_t uAl = uAh + TILE_B;
        const uint32_t uBh = uAh + NP * TILE_B;

#pragma unroll
        for (int kk = 0; kk < GBK; kk += 16) {
            uint32_t ah[MT][4], al[MT][4], bh[NT][2];
#pragma unroll
            for (int mi = 0; mi < MT; mi++) {
                uint32_t off = (uint32_t)(((wm + mi * 16 + aRow) * GST + kk + aCol) * 2);
                ldmx4(ah[mi], uAh + off);
                if (NP == 2) ldmx4(al[mi], uAl + off);
            }
#pragma unroll
            for (int j = 0; j < NT / 2; j++) {
                uint32_t off = (uint32_t)(((wn + j * 16 + bRow) * GST + kk + bCol) * 2);
                uint32_t rh[4];
                ldmx4(rh, uBh + off);
                bh[j * 2][0] = rh[0]; bh[j * 2][1] = rh[1];
                bh[j * 2 + 1][0] = rh[2]; bh[j * 2 + 1][1] = rh[3];
            }
#pragma unroll
            for (int mi = 0; mi < MT; mi++)
#pragma unroll
                for (int nj = 0; nj < NT; nj++) {
                    mma_h(acc[mi][nj], ah[mi], bh[nj]);
                    if (NP == 2) mma_h(acc[mi][nj], al[mi], bh[nj]);
                }
        }
    }
#undef ISSUE_STAGE

    const int er = lane >> 2;
    const int ec = (lane & 3) * 2;
#pragma unroll
    for (int mi = 0; mi < MT; mi++)
#pragma unroll
        for (int nj = 0; nj < NT; nj++) {
            float v0 = acc[mi][nj][0], v1 = acc[mi][nj][1];
            float v2 = acc[mi][nj][2], v3 = acc[mi][nj][3];
            const int gm = m0 + wm + mi * 16 + er;
            const int n  = n0 + wn + nj * 8 + ec;
            if (mode == 0) {
                float* p0 = C + (size_t)gm * N + n;
                *(float2*)p0           = make_float2(v0, v1);
                *(float2*)(p0 + 8 * N) = make_float2(v2, v3);
            } else {
                if (n < NH * HD + NKV * HD) {
                    const int p = (n & 63) >> 1;
                    const int t0 = gm & (T_ - 1);
                    const int t1 = (gm + 8) & (T_ - 1);
                    float c0 = cosb[t0 * 32 + p], s0 = sinb[t0 * 32 + p];
                    float c1 = cosb[t1 * 32 + p], s1 = sinb[t1 * 32 + p];
                    float e = v0, o = v1;
                    v0 = e * c0 - o * s0; v1 = e * s0 + o * c0;
                    e = v2; o = v3;
                    v2 = e * c1 - o * s1; v3 = e * s1 + o * c1;
                }
                if (n < NH * HD) {
                    v0 *= QSCALE; v1 *= QSCALE; v2 *= QSCALE; v3 *= QSCALE;
                    split_store_h(g_qh, g_ql, (size_t)gm * (NH * HD) + n, v0, v1);
                    split_store_h(g_qh, g_ql, (size_t)(gm + 8) * (NH * HD) + n, v2, v3);
                } else if (n < NH * HD + NKV * HD) {
                    int nn = n - NH * HD;
                    store_h2(g_kh, (size_t)gm * (NKV * HD) + nn, v0, v1);
                    store_h2(g_kh, (size_t)(gm + 8) * (NKV * HD) + nn, v2, v3);
                } else {
                    int nn = n - NH * HD - NKV * HD;
                    store_h2(g_vh, (size_t)gm * (NKV * HD) + nn, v0, v1);
                    store_h2(g_vh, (size_t)(gm + 8) * (NKV * HD) + nn, v2, v3);
                }
            }
        }
}

// ---------------------------------------------------------------------------
// Causal GQA flash attention, fp16 2-product, 2-stage KV pipeline (R13 core,
// 3 CTAs/SM). Epilogue now stores single fp16 output (Wo uses NP=1).
// ---------------------------------------------------------------------------
#define NEG_BIG (-1e30f)
#define AST 72
#define ATILE_B (64 * AST * 2)
#define ATTN_SMEM (4 * ATILE_B)   // 36864 B

__global__ void __launch_bounds__(128, 3) attn_hmma()
{
    const int qb = (T_ / 64 - 1) - blockIdx.x;   // long CTAs first
    const int bh = blockIdx.y;
    const int b = bh >> 5, h = bh & 31;
    const int kvh = h >> 2;

    extern __shared__ __align__(16) __half asm_[];
    const uint32_t uKV = smem_u32(asm_);

    const int tid  = threadIdx.x;
    const int wid  = tid >> 5;
    const int lane = tid & 31;

#define KVTILE(st, t) (uKV + (uint32_t)(((st) * 2 + (t)) * ATILE_B))

    const int aRow = (lane & 7) + ((lane >> 3) & 1) * 8;
    const int aCol = (lane >> 4) * 8;
    const int kRow = (lane & 7) + ((lane >> 4) & 1) * 8;
    const int kCol = ((lane >> 3) & 1) * 8;
    const int vRow = (lane & 7) + ((lane >> 3) & 1) * 8;
    const int vCol = ((lane >> 4) & 1) * 8;

    // --- prologue: stage Q (hi,lo) through stage-1 tiles, then release ---
    {
        const size_t qrow = ((size_t)(b * T_) + qb * 64);
        for (int f = tid; f < 512; f += 128) {
            int r = f >> 3, c = f & 7;
            size_t off = (qrow + r) * (NH * HD) + h * HD + c * 8;
            uint32_t d = (uint32_t)((r * AST + c * 8) * 2);
            cp16(KVTILE(1, 0) + d, g_qh + off);
            cp16(KVTILE(1, 1) + d, g_ql + off);
        }
    }
    CP_COMMIT();
    CP_WAIT(0);
    __syncthreads();

    uint32_t qh[4][4], ql[4][4];
#pragma unroll
    for (int kk = 0; kk < 4; kk++) {
        uint32_t off = (uint32_t)(((wid * 16 + aRow) * AST + kk * 16 + aCol) * 2);
        ldmx4(qh[kk], KVTILE(1, 0) + off);
        ldmx4(ql[kk], KVTILE(1, 1) + off);
    }
    __syncthreads();   // Q region free for KV reuse

#define ISSUE_KV(st, kb)                                                    \
    {                                                                       \
        size_t rowb = ((size_t)(b * T_) + (size_t)(kb) * 64);               \
        for (int f = tid; f < 512; f += 128) {                              \
            int r = f >> 3, c = f & 7;                                      \
            size_t off = (rowb + r) * (NKV * HD) + kvh * HD + c * 8;        \
            uint32_t d = (uint32_t)((r * AST + c * 8) * 2);                 \
            cp16(KVTILE(st, 0) + d, g_kh + off);                            \
            cp16(KVTILE(st, 1) + d, g_vh + off);                            \
        }                                                                   \
    }
    ISSUE_KV(0, 0)
    CP_COMMIT();

    float o[8][4];
#pragma unroll
    for (int j = 0; j < 8; j++)
#pragma unroll
        for (int c = 0; c < 4; c++) o[j][c] = 0.0f;
    float m[2] = {NEG_BIG, NEG_BIG}, l[2] = {0.0f, 0.0f};

    const int r0 = lane >> 2;
    const int c0 = (lane & 3) * 2;

    for (int kb = 0; kb <= qb; kb++) {
        CP_WAIT(0);
        __syncthreads();
        if (kb < qb) {
            ISSUE_KV((kb + 1) & 1, kb + 1)
            CP_COMMIT();
        }

        const uint32_t uKh = KVTILE(kb & 1, 0);
        const uint32_t uVh = KVTILE(kb & 1, 1);

        float s[8][4];
#pragma unroll
        for (int j = 0; j < 8; j++)
#pragma unroll
            for (int c = 0; c < 4; c++) s[j][c] = 0.0f;

#pragma unroll
        for (int kk = 0; kk < 4; kk++) {
#pragma unroll
            for (int g = 0; g < 4; g++) {
                uint32_t off = (uint32_t)(((g * 16 + kRow) * AST + kk * 16 + kCol) * 2);
                uint32_t kf[4];
                ldmx4(kf, uKh + off);
                mma_h(s[2 * g],     qh[kk], kf);
                mma_h(s[2 * g],     ql[kk], kf);
                mma_h(s[2 * g + 1], qh[kk], kf + 2);
                mma_h(s[2 * g + 1], ql[kk], kf + 2);
            }
        }

        if (kb == qb) {
            const int qr = wid * 16 + r0;
#pragma unroll
            for (int j = 0; j < 8; j++) {
                int col = j * 8 + c0;
                if (col     > qr)     s[j][0] = NEG_BIG;
                if (col + 1 > qr)     s[j][1] = NEG_BIG;
                if (col     > qr + 8) s[j][2] = NEG_BIG;
                if (col + 1 > qr + 8) s[j][3] = NEG_BIG;
            }
        }

        // online softmax in base-2
#pragma unroll
        for (int hh = 0; hh < 2; hh++) {
            float rm = NEG_BIG;
#pragma unroll
            for (int j = 0; j < 8; j++)
                rm = fmaxf(rm, fmaxf(s[j][2 * hh], s[j][2 * hh + 1]));
            rm = fmaxf(rm, __shfl_xor_sync(0xffffffffu, rm, 1));
            rm = fmaxf(rm, __shfl_xor_sync(0xffffffffu, rm, 2));
            float mnew = fmaxf(m[hh], rm);
            float corr = exp2f(m[hh] - mnew);
            float sum = 0.0f;
#pragma unroll
            for (int j = 0; j < 8; j++) {
                float p0 = exp2f(s[j][2 * hh]     - mnew);
                float p1 = exp2f(s[j][2 * hh + 1] - mnew);
                s[j][2 * hh] = p0; s[j][2 * hh + 1] = p1;
                sum += p0 + p1;
            }
            sum += __shfl_xor_sync(0xffffffffu, sum, 1);
            sum += __shfl_xor_sync(0xffffffffu, sum, 2);
            l[hh] = l[hh] * corr + sum;
            m[hh] = mnew;
#pragma unroll
            for (int j = 0; j < 8; j++) {
                o[j][2 * hh] *= corr; o[j][2 * hh + 1] *= corr;
            }
        }

        // PV: P split exact fp16 hi/lo, V single fp16
#pragma unroll
        for (int kk = 0; kk < 4; kk++) {
            uint32_t pha[4], pla[4];
#pragma unroll
            for (int t = 0; t < 2; t++) {
                int j = 2 * kk + t;
                __half2 hA = __floats2half2_rn(s[j][0], s[j][1]);
                float2 fA = __half22float2(hA);
                __half2 lA = __floats2half2_rn(s[j][0] - fA.x, s[j][1] - fA.y);
                __half2 hB = __floats2half2_rn(s[j][2], s[j][3]);
                float2 fB = __half22float2(hB);
                __half2 lB = __floats2half2_rn(s[j][2] - fB.x, s[j][3] - fB.y);
                pha[2 * t]     = *(uint32_t*)&hA;
                pha[2 * t + 1] = *(uint32_t*)&hB;
                pla[2 * t]     = *(uint32_t*)&lA;
                pla[2 * t + 1] = *(uint32_t*)&lB;
            }
#pragma unroll
            for (int g = 0; g < 4; g++) {
                uint32_t off = (uint32_t)(((kk * 16 + vRow) * AST + g * 16 + vCol) * 2);
                uint32_t vf[4];
                ldmx4t(vf, uVh + off);
                mma_h(o[2 * g],     pha, vf);
                mma_h(o[2 * g],     pla, vf);
                mma_h(o[2 * g + 1], pha, vf + 2);
                mma_h(o[2 * g + 1], pla, vf + 2);
            }
        }
    }
#undef ISSUE_KV
#undef KVTILE

    // Single-fp16 output (Wo GEMM consumes as NP=1)
#pragma unroll
    for (int hh = 0; hh < 2; hh++) {
        float inv = 1.0f / l[hh];
        size_t tok = (size_t)(b * T_) + qb * 64 + wid * 16 + r0 + hh * 8;
#pragma unroll
        for (int j = 0; j < 8; j++) {
            float v0 = o[j][2 * hh] * inv;
            float v1 = o[j][2 * hh + 1] * inv;
            size_t off = tok * (NH * HD) + h * HD + j * 8 + c0;
            store_h2(g_oh, off, v0, v1);
        }
    }
}

// ---------------------------------------------------------------------------
// Launch
// ---------------------------------------------------------------------------
extern "C" void kernel_launch(void* const* d_in, const int* in_sizes, int n_in,
                              void* d_out, int out_size)
{
    const float* x    = (const float*)d_in[0];
    const float* cosb = (const float*)d_in[1];
    const float* sinb = (const float*)d_in[2];
    const float* Wq   = (const float*)d_in[3];
    const float* Wk   = (const float*)d_in[4];
    const float* Wv   = (const float*)d_in[5];
    const float* Wo   = (const float*)d_in[6];
    float* out = (float*)d_out;

    __half *xh, *wqkvh, *woh, *oh;
    cudaGetSymbolAddress((void**)&xh, g_xh);
    cudaGetSymbolAddress((void**)&wqkvh, g_wqkvh);
    cudaGetSymbolAddress((void**)&woh, g_woh);
    cudaGetSymbolAddress((void**)&oh, g_oh);

    cudaFuncSetAttribute(gemm_h<1>, cudaFuncAttributeMaxDynamicSharedMemorySize,
                         2 * 2 * TILE_B);
    cudaFuncSetAttribute(gemm_h<2>, cudaFuncAttributeMaxDynamicSharedMemorySize,
                         2 * 3 * TILE_B);
    cudaFuncSetAttribute(attn_hmma, cudaFuncAttributeMaxDynamicSharedMemorySize,
                         ATTN_SMEM);

    const int M = B_ * T_;  // 4096

    // Merged conversions
    cvt_all_kernel<<<(NCVT + 255) / 256, 256>>>(
        (const float4*)x, (const float4*)Wq, (const float4*)Wk,
        (const float4*)Wv, (const float4*)Wo,
        (uint2*)xh, (uint2*)wqkvh, (uint2*)woh);

    // Fused QKV projection (single fp16 product; RoPE/scale/split epilogue)
    gemm_h<1><<<dim3(NQKV / 128, M / 128), 256, 2 * 2 * TILE_B>>>(
        xh, nullptr, wqkvh, nullptr, M, NQKV, DIM_, cosb, sinb, 1);

    // Attention (fp16 2-product HMMA, 2-stage KV pipeline, 3 CTAs/SM)
    attn_hmma<<<dim3(T_ / 64, B_ * NH), 128, ATTN_SMEM>>>();

    // Output projection (single fp16 product) -> fp32 d_out
    gemm_h<1><<<dim3(DIM_ / 128, M / 128), 256, 2 * 2 * TILE_B>>>(
        oh, nullptr, woh, out, M, DIM_, DIM_, cosb, sinb, 0);
}